// round 10
// baseline (speedup 1.0000x reference)
#include <cuda_runtime.h>
#include <stdint.h>

// GLCMAttention round 10: angle-split thread pairs.
//  k1: 512 threads/block. Threads t<256 do angles 0,1 (bytes 0,1); threads
//      t>=256 do angles 2,3 (bytes 2,3) for the SAME pixels (dup loads are
//      L1-hot). 64KB u8 hist shared by pairs -> 3 CTAs/SM, 48 warps/SM.
//  k2: out = x * g_scale[bc], grid 2048, streaming (~72% DRAM, at roofline).
//
// hist layout (bank == owner-lane for every access):
//   byte addr = warpslot<<13 | (q*8+qs)<<7 | lane<<2 | angle
// warpslot = warp & 7 (warps w and w+8 share a slot, disjoint bytes).

#define HIST_BYTES 65536
#define SMEM_TOTAL (HIST_BYTES + 256*4 + 16*4 + 16)

__device__ float g_scale[512];

__device__ __forceinline__ unsigned q7(float v) { return (unsigned)(int)(v * 7.0f); }

// Thread t (<256) sums counter-id t across all 8 warp-slot regions.
__device__ __forceinline__ unsigned flush_hist(const unsigned char* hist,
                                               int t, int lane)
{
    unsigned acc = 0;
    const unsigned sel = 1u << ((t & 3) * 8);          // extract byte 'angle'
    const unsigned pairbase = (unsigned)(t >> 2) << 7; // pair row (128B)
    const unsigned kst = (unsigned)(lane >> 2) & 7u;
    #pragma unroll
    for (int w = 0; w < 8; ++w) {
        unsigned base = ((unsigned)w << 13) | pairbase;
        #pragma unroll
        for (int k = 0; k < 8; ++k) {
            unsigned kk = ((unsigned)k + kst) & 7u;
            uint4 v = *(const uint4*)(hist + base + (kk << 4));
            acc = __dp4a(v.x, sel, acc);
            acc = __dp4a(v.y, sel, acc);
            acc = __dp4a(v.z, sel, acc);
            acc = __dp4a(v.w, sel, acc);
        }
    }
    return acc;
}

// Load strip-local row R (8 floats) into float array DF, zeros if OOB.
#define LOADA(DF, R)                                                         \
    {                                                                        \
        float4 aa = make_float4(0.f,0.f,0.f,0.f);                            \
        float4 bb = make_float4(0.f,0.f,0.f,0.f);                            \
        if (((R) <= 32) && ((grow + (R)) < 256)) {                           \
            const float4* p_ = (const float4*)(rowbase + (size_t)(R) * 256); \
            aa = p_[0]; bb = p_[1];                                          \
        }                                                                    \
        DF[0]=aa.x; DF[1]=aa.y; DF[2]=aa.z; DF[3]=aa.w;                      \
        DF[4]=bb.x; DF[5]=bb.y; DF[6]=bb.z; DF[7]=bb.w;                      \
    }

// Quantize float array SF -> unsigned array DQ + warp-edge shfls.
#define QUANTA(DQ, SF, LOUT, ROUT)                                           \
    {                                                                        \
        _Pragma("unroll")                                                    \
        for (int k_ = 0; k_ < 8; ++k_) DQ[k_] = q7(SF[k_]);                  \
        LOUT = __shfl_up_sync(0xFFFFFFFFu, DQ[7], 1);                        \
        if (lane == 0)  LOUT = 0u;                                           \
        ROUT = __shfl_down_sync(0xFFFFFFFFu, DQ[0], 1);                      \
        if (lane == 31) ROUT = 0u;                                           \
    }

// One pipeline step: quantize row Y+2 (from FB), prefetch row Y+3 into FB,
// RMW row Y for this thread's two angles, rotate.
#define STEPH(Y)                                                             \
    {                                                                        \
        unsigned t8[8], Lt, Rt;                                              \
        QUANTA(t8, fb, Lt, Rt)                                               \
        LOADA(fb, (Y)+3)                                                     \
        if (half == 0) {                                                     \
            _Pragma("unroll")                                                \
            for (int j = 0; j < 8; ++j) {                                    \
                unsigned char* b = hb + (qc[j] << 10);                       \
                unsigned ql_ = j ? qc[j-1] : Lc;                             \
                unsigned nl_ = j ? qn[j-1] : Ln;                             \
                unsigned char* pa = b + (ql_ << 7);                          \
                unsigned char* pb = b + (nl_ << 7) + 1;                      \
                unsigned va = *pa, vb = *pb;                                 \
                *pa = (unsigned char)(va + 1u);                              \
                *pb = (unsigned char)(vb + 1u);                              \
            }                                                                \
        } else {                                                             \
            _Pragma("unroll")                                                \
            for (int j = 0; j < 8; ++j) {                                    \
                unsigned char* b = hb + (qc[j] << 10);                       \
                unsigned nr_ = (j < 7) ? qn[j+1] : Rn;                       \
                unsigned char* pa = b + (qn[j] << 7);                        \
                unsigned char* pb = b + (nr_  << 7) + 1;                     \
                unsigned va = *pa, vb = *pb;                                 \
                *pa = (unsigned char)(va + 1u);                              \
                *pb = (unsigned char)(vb + 1u);                              \
            }                                                                \
        }                                                                    \
        _Pragma("unroll")                                                    \
        for (int k_ = 0; k_ < 8; ++k_) { qc[k_] = qn[k_]; qn[k_] = t8[k_]; } \
        Lc = Ln; Ln = Lt; Rn = Rt;                                           \
    }

__global__ void __launch_bounds__(512, 3)
glcm_hist_kernel(const float* __restrict__ x,
                 const float* __restrict__ W1,
                 const float* __restrict__ W2)
{
    extern __shared__ unsigned char smem[];
    unsigned char* hist   = smem;
    unsigned*      totals = (unsigned*)(smem + HIST_BYTES);
    float*         feats  = (float*)(totals + 256);

    const int t    = threadIdx.x;
    const int lane = t & 31;
    const int half = t >> 8;             // 0: angles 0,1   1: angles 2,3
    const int w    = (t >> 5) & 7;       // warp slot (pairs share)
    const int bc   = blockIdx.x;
    const float* xp = x + (size_t)bc * 65536;

    // ---- zero hist (4096 uint4 / 512 threads) ----
    uint4* h4 = (uint4*)hist;
    #pragma unroll
    for (int i = 0; i < 8; ++i) h4[t + (i << 9)] = make_uint4(0u,0u,0u,0u);
    __syncthreads();

    unsigned char* hb = hist + (w << 13) + (lane << 2) + (half << 1);

    const int grow = w << 5;                       // strip's global row 0
    const float* rowbase = xp + grow * 256 + (lane << 3);

    // ---- prologue: rows 0,1 quantized; row 2 floats prefetched ----
    unsigned qc[8], qn[8], Lc, Ln, Rn;
    float fb[8];
    {
        unsigned dum;
        LOADA(fb, 0)
        QUANTA(qc, fb, Lc, dum)
        (void)dum;
        LOADA(fb, 1)
        QUANTA(qn, fb, Ln, Rn)
    }
    LOADA(fb, 2)

    unsigned acc = 0;

    // ---- phase 1: rows 0..15 (max 8*16=128 per u8 counter) ----
    #pragma unroll 2
    for (int y = 0; y < 16; ++y) STEPH(y)

    __syncthreads();
    if (t < 256) acc += flush_hist(hist, t, lane);
    __syncthreads();
    #pragma unroll
    for (int i = 0; i < 8; ++i) h4[t + (i << 9)] = make_uint4(0u,0u,0u,0u);
    __syncthreads();

    // ---- phase 2: rows 16..31 ----
    #pragma unroll 2
    for (int y = 16; y < 32; ++y) STEPH(y)

    __syncthreads();
    if (t < 256) {
        acc += flush_hist(hist, t, lane);
        totals[t] = acc;
    }
    __syncthreads();

    // ---- features: warp 0, lane l -> angle = l>>3, row i = l&7 ----
    if (t < 32) {
        int angle = t >> 3;
        int sub   = t & 7;
        const float inv = 1.0f / 65536.0f;
        float fi = (float)sub;
        float contrast = 0.f, homog = 0.f, energy = 0.f, corr = 0.f;
        #pragma unroll
        for (int j = 0; j < 8; ++j) {
            float p = (float)totals[(((sub << 3) + j) << 2) + angle] * inv;
            float d = fi - (float)j;
            contrast += d * d * p;
            homog    += p / (1.0f + fabsf(d));
            energy   += p * p;
            corr     += (fi - 3.5f) * ((float)j - 3.5f) * p;
        }
        #pragma unroll
        for (int off = 4; off; off >>= 1) {
            contrast += __shfl_down_sync(0xFFFFFFFFu, contrast, off);
            homog    += __shfl_down_sync(0xFFFFFFFFu, homog,    off);
            energy   += __shfl_down_sync(0xFFFFFFFFu, energy,   off);
            corr     += __shfl_down_sync(0xFFFFFFFFu, corr,     off);
        }
        if (sub == 0) {
            feats[angle * 4 + 0] = contrast;
            feats[angle * 4 + 1] = homog;
            feats[angle * 4 + 2] = energy;
            feats[angle * 4 + 3] = corr * (1.0f / 6.000001f);  // /(std^2+1e-6)
        }
    }
    __syncthreads();

    // ---- MLP diagonal -> g_scale[bc] ----
    if (t < 16) {
        float h = 0.f;
        #pragma unroll
        for (int f = 0; f < 16; ++f) h += feats[f] * W1[f * 16 + t];
        h = fmaxf(h, 0.0f);
        int c = bc & 63;
        float v = h * W2[t * 64 + c];
        #pragma unroll
        for (int off = 8; off; off >>= 1)
            v += __shfl_down_sync(0x0000FFFFu, v, off);
        if (t == 0)
            g_scale[bc] = 1.0f + 1.0f / (1.0f + expf(-v));
    }
}

// k2: pure streaming scale. 4 blocks/image, 2048 blocks.
__global__ void __launch_bounds__(256)
glcm_scale_kernel(const float* __restrict__ x, float* __restrict__ out)
{
    const int blk = blockIdx.x;
    const float s = g_scale[blk >> 2];
    const float4* xs = (const float4*)x + (size_t)blk * 4096;
    float4*       os = (float4*)out     + (size_t)blk * 4096;
    const int t = threadIdx.x;
    #pragma unroll
    for (int k = 0; k < 16; ++k) {
        int i = t + (k << 8);
        float4 v = xs[i];
        v.x *= s; v.y *= s; v.z *= s; v.w *= s;
        os[i] = v;
    }
}

extern "C" void kernel_launch(void* const* d_in, const int* in_sizes, int n_in,
                              void* d_out, int out_size)
{
    (void)in_sizes; (void)n_in; (void)out_size;
    const float* x  = (const float*)d_in[0];
    const float* W1 = (const float*)d_in[1];
    const float* W2 = (const float*)d_in[2];
    float* out = (float*)d_out;

    cudaFuncSetAttribute(glcm_hist_kernel,
                         cudaFuncAttributeMaxDynamicSharedMemorySize, SMEM_TOTAL);
    glcm_hist_kernel<<<512, 512, SMEM_TOTAL>>>(x, W1, W2);
    glcm_scale_kernel<<<2048, 256>>>(x, out);
}

// round 11
// speedup vs baseline: 1.5602x; 1.5602x over previous
#include <cuda_runtime.h>
#include <stdint.h>

// GLCMAttention round 11: R8 champion hist kernel with the streaming scale
// fused into the tail (per-block: hist -> feats -> MLP -> out = x*s).
// Output streaming of finished CTAs overlaps hist latency stalls of the
// other 2 resident CTAs per SM.
//
// hist layout (bank == owner-lane for every access):
//   byte addr = warp<<13 | (q*8+qs)<<7 | lane<<2 | angle

#define HIST_BYTES 65536
#define SMEM_TOTAL (HIST_BYTES + 256*4 + 16*4 + 16)

__device__ __forceinline__ unsigned q7(float v) { return (unsigned)(int)(v * 7.0f); }

// Thread t sums counter-id t across all 256 per-thread regions.
__device__ __forceinline__ unsigned flush_hist(const unsigned char* hist,
                                               int t, int lane)
{
    unsigned acc = 0;
    const unsigned sel = 1u << ((t & 3) * 8);          // extract byte 'angle'
    const unsigned pairbase = (unsigned)(t >> 2) << 7; // pair row (128B)
    const unsigned kst = (unsigned)(lane >> 2) & 7u;
    #pragma unroll
    for (int w = 0; w < 8; ++w) {
        unsigned base = ((unsigned)w << 13) | pairbase;
        #pragma unroll
        for (int k = 0; k < 8; ++k) {
            unsigned kk = ((unsigned)k + kst) & 7u;
            uint4 v = *(const uint4*)(hist + base + (kk << 4));
            acc = __dp4a(v.x, sel, acc);
            acc = __dp4a(v.y, sel, acc);
            acc = __dp4a(v.z, sel, acc);
            acc = __dp4a(v.w, sel, acc);
        }
    }
    return acc;
}

// One pixel: 4 angle counters = 4 distinct bytes; loads grouped before stores.
#define PIXEL(QV, A0, A1, A2, A3)                                            \
    {                                                                        \
        unsigned char* b = hb + ((QV) << 10);                                \
        unsigned char* pa = b + ((A0) << 7);                                 \
        unsigned char* pb = b + ((A1) << 7) + 1;                             \
        unsigned char* pc = b + ((A2) << 7) + 2;                             \
        unsigned char* pd = b + ((A3) << 7) + 3;                             \
        unsigned va = *pa, vb = *pb, vc = *pc, vd = *pd;                     \
        *pa = (unsigned char)(va + 1u);                                      \
        *pb = (unsigned char)(vb + 1u);                                      \
        *pc = (unsigned char)(vc + 1u);                                      \
        *pd = (unsigned char)(vd + 1u);                                      \
    }

// Load strip-local row R (8 floats for this lane) or zeros if out of image.
#define LOADROW(D0,D1,D2,D3,D4,D5,D6,D7,R)                                   \
    {                                                                        \
        float4 aa = make_float4(0.f,0.f,0.f,0.f);                            \
        float4 bb = make_float4(0.f,0.f,0.f,0.f);                            \
        if (((R) <= 32) && ((grow + (R)) < 256)) {                           \
            const float4* p = (const float4*)(rowbase + (size_t)(R) * 256);  \
            aa = p[0]; bb = p[1];                                            \
        }                                                                    \
        D0=aa.x; D1=aa.y; D2=aa.z; D3=aa.w;                                  \
        D4=bb.x; D5=bb.y; D6=bb.z; D7=bb.w;                                  \
    }

// Quantize a row + its warp-edge shfls.
#define QUANTROW(S0,S1,S2,S3,S4,S5,S6,S7)                                    \
    t0=q7(S0); t1=q7(S1); t2=q7(S2); t3=q7(S3);                              \
    t4=q7(S4); t5=q7(S5); t6=q7(S6); t7=q7(S7);                              \
    Lt = __shfl_up_sync(0xFFFFFFFFu, t7, 1);   if (lane == 0)  Lt = 0u;      \
    Rt = __shfl_down_sync(0xFFFFFFFFu, t0, 1); if (lane == 31) Rt = 0u;

// Pipeline step: quantize row Y+2 (from S regs), prefetch row Y+4 (into S
// regs), RMW row Y (qc vs qn), rotate.
#define STEP(Y,S0,S1,S2,S3,S4,S5,S6,S7)                                      \
    {                                                                        \
        unsigned t0,t1,t2,t3,t4,t5,t6,t7, Lt, Rt;                            \
        QUANTROW(S0,S1,S2,S3,S4,S5,S6,S7)                                    \
        LOADROW(S0,S1,S2,S3,S4,S5,S6,S7,(Y)+4)                               \
        PIXEL(qc0, Lc,  Ln,  qn0, qn1)                                       \
        PIXEL(qc1, qc0, qn0, qn1, qn2)                                       \
        PIXEL(qc2, qc1, qn1, qn2, qn3)                                       \
        PIXEL(qc3, qc2, qn2, qn3, qn4)                                       \
        PIXEL(qc4, qc3, qn3, qn4, qn5)                                       \
        PIXEL(qc5, qc4, qn4, qn5, qn6)                                       \
        PIXEL(qc6, qc5, qn5, qn6, qn7)                                       \
        PIXEL(qc7, qc6, qn6, qn7, Rn)                                        \
        qc0=qn0; qc1=qn1; qc2=qn2; qc3=qn3;                                  \
        qc4=qn4; qc5=qn5; qc6=qn6; qc7=qn7; Lc=Ln;                           \
        qn0=t0; qn1=t1; qn2=t2; qn3=t3;                                      \
        qn4=t4; qn5=t5; qn6=t6; qn7=t7; Ln=Lt; Rn=Rt;                        \
    }

__global__ void __launch_bounds__(256, 3)
glcm_attn_kernel(const float* __restrict__ x,
                 const float* __restrict__ W1,
                 const float* __restrict__ W2,
                 float* __restrict__ out)
{
    extern __shared__ unsigned char smem[];
    unsigned char* hist   = smem;
    unsigned*      totals = (unsigned*)(smem + HIST_BYTES);
    float*         feats  = (float*)(totals + 256);
    float*         scalep = feats + 16;

    const int t = threadIdx.x, lane = t & 31, w = t >> 5;
    const int bc = blockIdx.x;
    const float* xp = x   + (size_t)bc * 65536;
    float*       op = out + (size_t)bc * 65536;

    // ---- zero hist ----
    uint4* h4 = (uint4*)hist;
    #pragma unroll
    for (int i = 0; i < 16; ++i) h4[t + (i << 8)] = make_uint4(0u,0u,0u,0u);
    __syncthreads();

    unsigned char* hb = hist + (w << 13) + (lane << 2);

    const int grow = w << 5;                       // strip's global row 0
    const float* rowbase = xp + grow * 256 + (lane << 3);

    // ---- prologue: rows 0,1 quantized; rows 2,3 prefetched ----
    unsigned qc0,qc1,qc2,qc3,qc4,qc5,qc6,qc7, Lc;
    unsigned qn0,qn1,qn2,qn3,qn4,qn5,qn6,qn7, Ln, Rn;
    float fa0,fa1,fa2,fa3,fa4,fa5,fa6,fa7;
    float fb0,fb1,fb2,fb3,fb4,fb5,fb6,fb7;
    {
        unsigned t0,t1,t2,t3,t4,t5,t6,t7, Lt, Rt;
        LOADROW(fa0,fa1,fa2,fa3,fa4,fa5,fa6,fa7, 0)
        QUANTROW(fa0,fa1,fa2,fa3,fa4,fa5,fa6,fa7)
        qc0=t0; qc1=t1; qc2=t2; qc3=t3; qc4=t4; qc5=t5; qc6=t6; qc7=t7;
        Lc = Lt; (void)Rt;
        LOADROW(fa0,fa1,fa2,fa3,fa4,fa5,fa6,fa7, 1)
        QUANTROW(fa0,fa1,fa2,fa3,fa4,fa5,fa6,fa7)
        qn0=t0; qn1=t1; qn2=t2; qn3=t3; qn4=t4; qn5=t5; qn6=t6; qn7=t7;
        Ln = Lt; Rn = Rt;
    }
    LOADROW(fa0,fa1,fa2,fa3,fa4,fa5,fa6,fa7, 2)
    LOADROW(fb0,fb1,fb2,fb3,fb4,fb5,fb6,fb7, 3)

    unsigned acc = 0;

    // ---- phase 1: rows 0..15 (max 8*16=128 per u8 counter) ----
    #pragma unroll 2
    for (int y = 0; y < 16; y += 2) {
        STEP(y,   fa0,fa1,fa2,fa3,fa4,fa5,fa6,fa7)
        STEP(y+1, fb0,fb1,fb2,fb3,fb4,fb5,fb6,fb7)
    }
    __syncthreads();
    acc += flush_hist(hist, t, lane);
    __syncthreads();
    #pragma unroll
    for (int i = 0; i < 16; ++i) h4[t + (i << 8)] = make_uint4(0u,0u,0u,0u);
    __syncthreads();

    // ---- phase 2: rows 16..31 ----
    #pragma unroll 2
    for (int y = 16; y < 32; y += 2) {
        STEP(y,   fa0,fa1,fa2,fa3,fa4,fa5,fa6,fa7)
        STEP(y+1, fb0,fb1,fb2,fb3,fb4,fb5,fb6,fb7)
    }
    __syncthreads();
    acc += flush_hist(hist, t, lane);
    totals[t] = acc;
    __syncthreads();

    // ---- features: warp 0, lane l -> angle = l>>3, row i = l&7 ----
    if (t < 32) {
        int angle = t >> 3;
        int sub   = t & 7;
        const float inv = 1.0f / 65536.0f;
        float fi = (float)sub;
        float contrast = 0.f, homog = 0.f, energy = 0.f, corr = 0.f;
        #pragma unroll
        for (int j = 0; j < 8; ++j) {
            float p = (float)totals[(((sub << 3) + j) << 2) + angle] * inv;
            float d = fi - (float)j;
            contrast += d * d * p;
            homog    += p / (1.0f + fabsf(d));
            energy   += p * p;
            corr     += (fi - 3.5f) * ((float)j - 3.5f) * p;
        }
        #pragma unroll
        for (int off = 4; off; off >>= 1) {
            contrast += __shfl_down_sync(0xFFFFFFFFu, contrast, off);
            homog    += __shfl_down_sync(0xFFFFFFFFu, homog,    off);
            energy   += __shfl_down_sync(0xFFFFFFFFu, energy,   off);
            corr     += __shfl_down_sync(0xFFFFFFFFu, corr,     off);
        }
        if (sub == 0) {
            feats[angle * 4 + 0] = contrast;
            feats[angle * 4 + 1] = homog;
            feats[angle * 4 + 2] = energy;
            feats[angle * 4 + 3] = corr * (1.0f / 6.000001f);  // /(std^2+1e-6)
        }
    }
    __syncthreads();

    // ---- MLP diagonal -> smem scale ----
    if (t < 16) {
        float h = 0.f;
        #pragma unroll
        for (int f = 0; f < 16; ++f) h += feats[f] * W1[f * 16 + t];
        h = fmaxf(h, 0.0f);
        int c = bc & 63;
        float v = h * W2[t * 64 + c];
        #pragma unroll
        for (int off = 8; off; off >>= 1)
            v += __shfl_down_sync(0x0000FFFFu, v, off);
        if (t == 0)
            *scalep = 1.0f + 1.0f / (1.0f + expf(-v));
    }
    __syncthreads();

    // ---- fused output: out = x * scale (streams while other CTAs hist) ----
    const float s = *scalep;
    const float4* xs = (const float4*)xp;
    float4*       os = (float4*)op;
    #pragma unroll 4
    for (int k = 0; k < 64; ++k) {
        int i = t + (k << 8);
        float4 v = xs[i];
        v.x *= s; v.y *= s; v.z *= s; v.w *= s;
        os[i] = v;
    }
}

extern "C" void kernel_launch(void* const* d_in, const int* in_sizes, int n_in,
                              void* d_out, int out_size)
{
    (void)in_sizes; (void)n_in; (void)out_size;
    const float* x  = (const float*)d_in[0];
    const float* W1 = (const float*)d_in[1];
    const float* W2 = (const float*)d_in[2];
    float* out = (float*)d_out;

    cudaFuncSetAttribute(glcm_attn_kernel,
                         cudaFuncAttributeMaxDynamicSharedMemorySize, SMEM_TOTAL);
    glcm_attn_kernel<<<512, 256, SMEM_TOTAL>>>(x, W1, W2, out);
}

// round 12
// speedup vs baseline: 1.6566x; 1.0618x over previous
#include <cuda_runtime.h>
#include <stdint.h>

// GLCMAttention round 12: quarter-image hist blocks (wave-packing fix),
// single flush (max count 64), atomicAdd combine, scale kernel with fused
// feats+MLP.
//   k0: zero g_totals
//   k1: grid 2048 (img*4+quarter), 64KB u8 hist, 3 CTAs/SM, 1 flush,
//       atomicAdd partial totals.
//   k2: grid 2048, per-block: feats+MLP from g_totals -> stream quarter.
//
// hist layout (bank == owner-lane for every access):
//   byte addr = warp<<13 | (q*8+qs)<<7 | lane<<2 | angle

#define HIST_BYTES 65536
#define SMEM_TOTAL (HIST_BYTES + 64)

__device__ unsigned g_totals[512 * 256];

__device__ __forceinline__ unsigned q7(float v) { return (unsigned)(int)(v * 7.0f); }

// Thread t sums counter-id t across all 256 per-thread regions.
__device__ __forceinline__ unsigned flush_hist(const unsigned char* hist,
                                               int t, int lane)
{
    unsigned acc = 0;
    const unsigned sel = 1u << ((t & 3) * 8);          // extract byte 'angle'
    const unsigned pairbase = (unsigned)(t >> 2) << 7; // pair row (128B)
    const unsigned kst = (unsigned)(lane >> 2) & 7u;
    #pragma unroll
    for (int w = 0; w < 8; ++w) {
        unsigned base = ((unsigned)w << 13) | pairbase;
        #pragma unroll
        for (int k = 0; k < 8; ++k) {
            unsigned kk = ((unsigned)k + kst) & 7u;
            uint4 v = *(const uint4*)(hist + base + (kk << 4));
            acc = __dp4a(v.x, sel, acc);
            acc = __dp4a(v.y, sel, acc);
            acc = __dp4a(v.z, sel, acc);
            acc = __dp4a(v.w, sel, acc);
        }
    }
    return acc;
}

// One pixel: 4 angle counters = 4 distinct bytes; loads grouped before stores.
#define PIXEL(QV, A0, A1, A2, A3)                                            \
    {                                                                        \
        unsigned char* b = hb + ((QV) << 10);                                \
        unsigned char* pa = b + ((A0) << 7);                                 \
        unsigned char* pb = b + ((A1) << 7) + 1;                             \
        unsigned char* pc = b + ((A2) << 7) + 2;                             \
        unsigned char* pd = b + ((A3) << 7) + 3;                             \
        unsigned va = *pa, vb = *pb, vc = *pc, vd = *pd;                     \
        *pa = (unsigned char)(va + 1u);                                      \
        *pb = (unsigned char)(vb + 1u);                                      \
        *pc = (unsigned char)(vc + 1u);                                      \
        *pd = (unsigned char)(vd + 1u);                                      \
    }

// Load strip-local row R (8 floats for this lane) or zeros if out of range.
// Strip is 8 rows; row 8 (first row of next strip) is needed as neighbor.
#define LOADROW(D0,D1,D2,D3,D4,D5,D6,D7,R)                                   \
    {                                                                        \
        float4 aa = make_float4(0.f,0.f,0.f,0.f);                            \
        float4 bb = make_float4(0.f,0.f,0.f,0.f);                            \
        if (((R) <= 8) && ((grow + (R)) < 256)) {                            \
            const float4* p = (const float4*)(rowbase + (size_t)(R) * 256);  \
            aa = p[0]; bb = p[1];                                            \
        }                                                                    \
        D0=aa.x; D1=aa.y; D2=aa.z; D3=aa.w;                                  \
        D4=bb.x; D5=bb.y; D6=bb.z; D7=bb.w;                                  \
    }

// Quantize a row + its warp-edge shfls.
#define QUANTROW(S0,S1,S2,S3,S4,S5,S6,S7)                                    \
    t0=q7(S0); t1=q7(S1); t2=q7(S2); t3=q7(S3);                              \
    t4=q7(S4); t5=q7(S5); t6=q7(S6); t7=q7(S7);                              \
    Lt = __shfl_up_sync(0xFFFFFFFFu, t7, 1);   if (lane == 0)  Lt = 0u;      \
    Rt = __shfl_down_sync(0xFFFFFFFFu, t0, 1); if (lane == 31) Rt = 0u;

// Pipeline step: quantize row Y+2 (from S regs), prefetch row Y+4 (into S
// regs), RMW row Y (qc vs qn), rotate.
#define STEP(Y,S0,S1,S2,S3,S4,S5,S6,S7)                                      \
    {                                                                        \
        unsigned t0,t1,t2,t3,t4,t5,t6,t7, Lt, Rt;                            \
        QUANTROW(S0,S1,S2,S3,S4,S5,S6,S7)                                    \
        LOADROW(S0,S1,S2,S3,S4,S5,S6,S7,(Y)+4)                               \
        PIXEL(qc0, Lc,  Ln,  qn0, qn1)                                       \
        PIXEL(qc1, qc0, qn0, qn1, qn2)                                       \
        PIXEL(qc2, qc1, qn1, qn2, qn3)                                       \
        PIXEL(qc3, qc2, qn2, qn3, qn4)                                       \
        PIXEL(qc4, qc3, qn3, qn4, qn5)                                       \
        PIXEL(qc5, qc4, qn4, qn5, qn6)                                       \
        PIXEL(qc6, qc5, qn5, qn6, qn7)                                       \
        PIXEL(qc7, qc6, qn6, qn7, Rn)                                        \
        qc0=qn0; qc1=qn1; qc2=qn2; qc3=qn3;                                  \
        qc4=qn4; qc5=qn5; qc6=qn6; qc7=qn7; Lc=Ln;                           \
        qn0=t0; qn1=t1; qn2=t2; qn3=t3;                                      \
        qn4=t4; qn5=t5; qn6=t6; qn7=t7; Ln=Lt; Rn=Rt;                        \
    }

__global__ void glcm_zero_kernel()
{
    int i = blockIdx.x * 256 + threadIdx.x;
    uint4* p = (uint4*)g_totals;     // 512*256 u32 = 32768 uint4
    p[i] = make_uint4(0u, 0u, 0u, 0u);
}

__global__ void __launch_bounds__(256, 3)
glcm_hist_kernel(const float* __restrict__ x)
{
    extern __shared__ unsigned char smem[];
    unsigned char* hist = smem;

    const int t = threadIdx.x, lane = t & 31, w = t >> 5;
    const int bx  = blockIdx.x;
    const int img = bx >> 2;
    const int qd  = bx & 3;
    const float* xp = x + (size_t)img * 65536;

    // ---- zero hist ----
    uint4* h4 = (uint4*)hist;
    #pragma unroll
    for (int i = 0; i < 16; ++i) h4[t + (i << 8)] = make_uint4(0u,0u,0u,0u);
    __syncthreads();

    unsigned char* hb = hist + (w << 13) + (lane << 2);

    const int grow = (qd << 6) + (w << 3);         // strip's global row 0
    const float* rowbase = xp + grow * 256 + (lane << 3);

    // ---- prologue: rows 0,1 quantized; rows 2,3 prefetched ----
    unsigned qc0,qc1,qc2,qc3,qc4,qc5,qc6,qc7, Lc;
    unsigned qn0,qn1,qn2,qn3,qn4,qn5,qn6,qn7, Ln, Rn;
    float fa0,fa1,fa2,fa3,fa4,fa5,fa6,fa7;
    float fb0,fb1,fb2,fb3,fb4,fb5,fb6,fb7;
    {
        unsigned t0,t1,t2,t3,t4,t5,t6,t7, Lt, Rt;
        LOADROW(fa0,fa1,fa2,fa3,fa4,fa5,fa6,fa7, 0)
        QUANTROW(fa0,fa1,fa2,fa3,fa4,fa5,fa6,fa7)
        qc0=t0; qc1=t1; qc2=t2; qc3=t3; qc4=t4; qc5=t5; qc6=t6; qc7=t7;
        Lc = Lt; (void)Rt;
        LOADROW(fa0,fa1,fa2,fa3,fa4,fa5,fa6,fa7, 1)
        QUANTROW(fa0,fa1,fa2,fa3,fa4,fa5,fa6,fa7)
        qn0=t0; qn1=t1; qn2=t2; qn3=t3; qn4=t4; qn5=t5; qn6=t6; qn7=t7;
        Ln = Lt; Rn = Rt;
    }
    LOADROW(fa0,fa1,fa2,fa3,fa4,fa5,fa6,fa7, 2)
    LOADROW(fb0,fb1,fb2,fb3,fb4,fb5,fb6,fb7, 3)

    // ---- 8 rows, single phase (max 8*8=64 per u8 counter) ----
    #pragma unroll 2
    for (int y = 0; y < 8; y += 2) {
        STEP(y,   fa0,fa1,fa2,fa3,fa4,fa5,fa6,fa7)
        STEP(y+1, fb0,fb1,fb2,fb3,fb4,fb5,fb6,fb7)
    }

    __syncthreads();
    unsigned acc = flush_hist(hist, t, lane);
    atomicAdd(&g_totals[img * 256 + t], acc);
}

// k2: per quarter-block: feats + MLP from g_totals (redundant per image,
// cheap & L2-hot), then stream out = x * s for this quarter.
__global__ void __launch_bounds__(256)
glcm_scale_kernel(const float* __restrict__ x,
                  const float* __restrict__ W1,
                  const float* __restrict__ W2,
                  float* __restrict__ out)
{
    __shared__ float feats[16];
    __shared__ float scale_s;

    const int t = threadIdx.x;
    const int bx  = blockIdx.x;
    const int img = bx >> 2;
    const int qd  = bx & 3;

    // ---- features: warp 0, lane l -> angle = l>>3, row i = l&7 ----
    if (t < 32) {
        int angle = t >> 3;
        int sub   = t & 7;
        const float inv = 1.0f / 65536.0f;
        float fi = (float)sub;
        float contrast = 0.f, homog = 0.f, energy = 0.f, corr = 0.f;
        const unsigned* tot = g_totals + img * 256;
        #pragma unroll
        for (int j = 0; j < 8; ++j) {
            float p = (float)__ldg(&tot[(((sub << 3) + j) << 2) + angle]) * inv;
            float d = fi - (float)j;
            contrast += d * d * p;
            homog    += p / (1.0f + fabsf(d));
            energy   += p * p;
            corr     += (fi - 3.5f) * ((float)j - 3.5f) * p;
        }
        #pragma unroll
        for (int off = 4; off; off >>= 1) {
            contrast += __shfl_down_sync(0xFFFFFFFFu, contrast, off);
            homog    += __shfl_down_sync(0xFFFFFFFFu, homog,    off);
            energy   += __shfl_down_sync(0xFFFFFFFFu, energy,   off);
            corr     += __shfl_down_sync(0xFFFFFFFFu, corr,     off);
        }
        if (sub == 0) {
            feats[angle * 4 + 0] = contrast;
            feats[angle * 4 + 1] = homog;
            feats[angle * 4 + 2] = energy;
            feats[angle * 4 + 3] = corr * (1.0f / 6.000001f);  // /(std^2+1e-6)
        }
    }
    __syncthreads();

    // ---- MLP diagonal ----
    if (t < 16) {
        float h = 0.f;
        #pragma unroll
        for (int f = 0; f < 16; ++f) h += feats[f] * W1[f * 16 + t];
        h = fmaxf(h, 0.0f);
        int c = img & 63;
        float v = h * W2[t * 64 + c];
        #pragma unroll
        for (int off = 8; off; off >>= 1)
            v += __shfl_down_sync(0x0000FFFFu, v, off);
        if (t == 0)
            scale_s = 1.0f + 1.0f / (1.0f + expf(-v));
    }
    __syncthreads();

    // ---- stream this quarter: out = x * s ----
    const float s = scale_s;
    const float4* xs = (const float4*)x + (size_t)bx * 4096;
    float4*       os = (float4*)out     + (size_t)bx * 4096;
    #pragma unroll
    for (int k = 0; k < 16; ++k) {
        int i = t + (k << 8);
        float4 v = xs[i];
        v.x *= s; v.y *= s; v.z *= s; v.w *= s;
        os[i] = v;
    }
}

extern "C" void kernel_launch(void* const* d_in, const int* in_sizes, int n_in,
                              void* d_out, int out_size)
{
    (void)in_sizes; (void)n_in; (void)out_size;
    const float* x  = (const float*)d_in[0];
    const float* W1 = (const float*)d_in[1];
    const float* W2 = (const float*)d_in[2];
    float* out = (float*)d_out;

    cudaFuncSetAttribute(glcm_hist_kernel,
                         cudaFuncAttributeMaxDynamicSharedMemorySize, SMEM_TOTAL);
    glcm_zero_kernel<<<128, 256>>>();
    glcm_hist_kernel<<<2048, 256, SMEM_TOTAL>>>(x);
    glcm_scale_kernel<<<2048, 256>>>(x, W1, W2, out);
}